// round 10
// baseline (speedup 1.0000x reference)
#include <cuda_runtime.h>
#include <cuda_bf16.h>
#include <cstdint>

#define NN      2048
#define RBF     32
#define TPB     256
#define MTILE   128
#define NTILES  (NN / MTILE)   // 16
#define APITCH  80             // bytes per 32-bf16 row; 20 banks step -> conflict-free ldmatrix

#define LOG2E 1.4426950408889634f
#define LN2   0.6931471805599453f

// ---------------- helpers ----------------
__device__ __forceinline__ uint32_t smem_u32(const void* p) {
    return (uint32_t)__cvta_generic_to_shared(p);
}
__device__ __forceinline__ void cp_async16(uint32_t saddr, const void* g) {
    asm volatile("cp.async.cg.shared.global [%0], [%1], 16;\n"
                 :: "r"(saddr), "l"(g) : "memory");
}
__device__ __forceinline__ void ldmatrix_x4(uint32_t addr, uint32_t& r0, uint32_t& r1,
                                            uint32_t& r2, uint32_t& r3) {
    asm volatile("ldmatrix.sync.aligned.m8n8.x4.shared.b16 {%0,%1,%2,%3}, [%4];"
                 : "=r"(r0), "=r"(r1), "=r"(r2), "=r"(r3) : "r"(addr));
}
__device__ __forceinline__ void mma_bf16(float& d0, float& d1, float& d2, float& d3,
                                         uint32_t a0, uint32_t a1, uint32_t a2, uint32_t a3,
                                         uint32_t b0, uint32_t b1) {
    asm volatile("mma.sync.aligned.m16n8k16.row.col.f32.bf16.bf16.f32 "
                 "{%0,%1,%2,%3}, {%4,%5,%6,%7}, {%8,%9}, {%0,%1,%2,%3};"
                 : "+f"(d0), "+f"(d1), "+f"(d2), "+f"(d3)
                 : "r"(a0), "r"(a1), "r"(a2), "r"(a3), "r"(b0), "r"(b1));
}
__device__ __forceinline__ float ex2f(float x) {
    float y; asm("ex2.approx.f32 %0, %1;" : "=f"(y) : "f"(x)); return y;
}
__device__ __forceinline__ float lg2f(float x) {
    float y; asm("lg2.approx.f32 %0, %1;" : "=f"(y) : "f"(x)); return y;
}
__device__ __forceinline__ uint32_t bits2(__nv_bfloat162 v) {
    return *(uint32_t*)&v;
}

// ---------------- kernel ----------------
// One block per 'a'. 16 tiles of 128 pairs. 8 warps, 16 MMA rows each.
// cp.async fp32 -> bf16 hi/lo split (80B pitch) -> mma.sync bf16 (3 split
// products) -> log2-domain softplus + W2 dot on fragments -> cross-product
// accumulate. B-hi fragments persist in regs; B-lo re-ldmatrix'd per k-step.
__global__ __launch_bounds__(TPB, 3) void f1o1_mma_kernel(
    const float* __restrict__ layer_input,  // [NN,1,3]
    const float* __restrict__ rbf,          // [NN,NN,RBF]
    const float* __restrict__ rij,          // [NN,NN,3]
    const float* __restrict__ W1,           // [RBF,RBF] (k,h)
    const float* __restrict__ b1,           // [RBF]
    const float* __restrict__ W2,           // [RBF,1]
    const float* __restrict__ b2,           // [1]
    float* __restrict__ out)                // [NN,1,3]
{
    __shared__ __align__(16) float stag[MTILE * RBF];   // 16 KB fp32 staging
    __shared__ __align__(16) char  AhT[MTILE * APITCH]; // 10 KB bf16 hi
    __shared__ __align__(16) char  AlT[MTILE * APITCH]; // 10 KB bf16 lo
    __shared__ __align__(16) char  BhT[RBF * APITCH];   // 2.5 KB W1^T hi
    __shared__ __align__(16) char  BlT[RBF * APITCH];   // 2.5 KB W1^T lo
    __shared__ __align__(16) float2 eb[RBF];            // {b1*log2e, w2*ln2}
    __shared__ float radbuf[MTILE];
    __shared__ float redbuf[3][4];

    const int tid  = threadIdx.x;
    const int lane = tid & 31;
    const int wid  = tid >> 5;
    const int a    = blockIdx.x;
    const uint32_t STAG = smem_u32(stag);
    const uint32_t AH = smem_u32(AhT), AL = smem_u32(AlT);
    const uint32_t BH = smem_u32(BhT), BL = smem_u32(BlT);

    // ---- build B = W1^T split hi/lo + folded epilogue constants ----
    for (int e = tid; e < RBF * RBF; e += TPB) {
        int k = e >> 5, h = e & 31;
        float w = W1[e];
        __nv_bfloat16 hb = __float2bfloat16(w);
        __nv_bfloat16 lb = __float2bfloat16(w - __bfloat162float(hb));
        *(unsigned short*)(BhT + h * APITCH + k * 2) = *(unsigned short*)&hb;
        *(unsigned short*)(BlT + h * APITCH + k * 2) = *(unsigned short*)&lb;
    }
    if (tid < RBF) eb[tid] = make_float2(b1[tid] * LOG2E, W2[tid] * LN2);
    const float bias2 = b2[0];

    // ---- prefetch tile 0 ----
    {
        const float4* g = (const float4*)(rbf + (size_t)a * NN * RBF);
        #pragma unroll
        for (int j = 0; j < 4; j++) {
            int f = tid + TPB * j;
            cp_async16(STAG + f * 16, g + f);
        }
        asm volatile("cp.async.commit_group;" ::: "memory");
    }
    __syncthreads();   // B tiles + eb ready

    // ---- per-thread folded constants: {b1e, w2l} for h = 8j+2c, +1 ----
    float4 ebv[4];
    {
        int c = lane & 3;
        #pragma unroll
        for (int j = 0; j < 4; j++)
            ebv[j] = *(const float4*)&eb[8 * j + 2 * c];
    }

    // ---- preload B-hi fragments: bh[j][s][r] (16 regs) ----
    uint32_t bh[4][2][2];
    {
        int q = lane >> 3;                 // matrix index within x4
        int l8 = lane & 7;
        #pragma unroll
        for (int s = 0; s < 2; s++) {
            // x4 #1: j=0,1 ; x4 #2: j=2,3 (q: joff=q>>1, khalf=q&1)
            uint32_t off0 = (uint32_t)((8 * (q >> 1) + l8) * APITCH
                                       + (16 * s + 8 * (q & 1)) * 2);
            ldmatrix_x4(BH + off0, bh[0][s][0], bh[0][s][1], bh[1][s][0], bh[1][s][1]);
            uint32_t off1 = (uint32_t)((8 * (2 + (q >> 1)) + l8) * APITCH
                                       + (16 * s + 8 * (q & 1)) * 2);
            ldmatrix_x4(BH + off1, bh[2][s][0], bh[2][s][1], bh[3][s][0], bh[3][s][1]);
        }
    }

    float o0 = 0.f, o1 = 0.f, o2 = 0.f;

    #pragma unroll 1
    for (int t = 0; t < NTILES; t++) {
        asm volatile("cp.async.wait_group 0;" ::: "memory");
        __syncthreads();

        // ---- convert fp32 staging -> bf16 hi/lo A tiles ----
        #pragma unroll
        for (int j = 0; j < 4; j++) {
            int f = tid + TPB * j;
            float4 v = ((const float4*)stag)[f];
            int row = f >> 3, kq = f & 7;
            __nv_bfloat162 h0 = __floats2bfloat162_rn(v.x, v.y);
            __nv_bfloat162 h1 = __floats2bfloat162_rn(v.z, v.w);
            float2 r0 = __bfloat1622float2(h0);
            float2 r1 = __bfloat1622float2(h1);
            __nv_bfloat162 l0 = __floats2bfloat162_rn(v.x - r0.x, v.y - r0.y);
            __nv_bfloat162 l1 = __floats2bfloat162_rn(v.z - r1.x, v.w - r1.y);
            *(uint2*)(AhT + row * APITCH + kq * 8) = make_uint2(bits2(h0), bits2(h1));
            *(uint2*)(AlT + row * APITCH + kq * 8) = make_uint2(bits2(l0), bits2(l1));
        }
        __syncthreads();

        // ---- prefetch next tile ----
        if (t + 1 < NTILES) {
            const float4* g = (const float4*)(rbf + ((size_t)a * NN + (t + 1) * MTILE) * RBF);
            #pragma unroll
            for (int j = 0; j < 4; j++) {
                int f = tid + TPB * j;
                cp_async16(STAG + f * 16, g + f);
            }
            asm volatile("cp.async.commit_group;" ::: "memory");
        }

        // ---- MMA: this warp's 16 rows. hidden = xh*Wh + xl*Wh + xh*Wl ----
        float d[4][4];
        #pragma unroll
        for (int j = 0; j < 4; j++)
            #pragma unroll
            for (int r = 0; r < 4; r++) d[j][r] = 0.f;

        const int rowbase = wid * 16;
        #pragma unroll
        for (int s = 0; s < 2; s++) {
            // A hi/lo fragments for k-half s
            uint32_t aoff = (uint32_t)((rowbase + (lane & 15)) * APITCH
                                       + (16 * s + 8 * (lane >> 4)) * 2);
            uint32_t ah0, ah1, ah2, ah3, al0, al1, al2, al3;
            ldmatrix_x4(AH + aoff, ah0, ah1, ah2, ah3);
            ldmatrix_x4(AL + aoff, al0, al1, al2, al3);

            // B-lo fragments for this s (transient)
            uint32_t bl[4][2];
            {
                int q = lane >> 3, l8 = lane & 7;
                uint32_t off0 = (uint32_t)((8 * (q >> 1) + l8) * APITCH
                                           + (16 * s + 8 * (q & 1)) * 2);
                ldmatrix_x4(BL + off0, bl[0][0], bl[0][1], bl[1][0], bl[1][1]);
                uint32_t off1 = (uint32_t)((8 * (2 + (q >> 1)) + l8) * APITCH
                                           + (16 * s + 8 * (q & 1)) * 2);
                ldmatrix_x4(BL + off1, bl[2][0], bl[2][1], bl[3][0], bl[3][1]);
            }

            #pragma unroll
            for (int j = 0; j < 4; j++) {
                mma_bf16(d[j][0], d[j][1], d[j][2], d[j][3],
                         ah0, ah1, ah2, ah3, bh[j][s][0], bh[j][s][1]);
                mma_bf16(d[j][0], d[j][1], d[j][2], d[j][3],
                         al0, al1, al2, al3, bh[j][s][0], bh[j][s][1]);
                mma_bf16(d[j][0], d[j][1], d[j][2], d[j][3],
                         ah0, ah1, ah2, ah3, bl[j][0], bl[j][1]);
            }
        }

        // ---- fragment epilogue: log2-domain softplus + W2 dot ----
        // softplus(s)*w2 = (max(u,0)+log2(1+2^-|u|)) * (w2*ln2), u = d*log2e + b1*log2e
        float sA = 0.f, sB = 0.f;   // rows g, g+8 of this warp's 16-row slice
        #pragma unroll
        for (int j = 0; j < 4; j++) {
            float u0 = fmaf(d[j][0], LOG2E, ebv[j].x);
            float u1 = fmaf(d[j][1], LOG2E, ebv[j].z);
            float u2 = fmaf(d[j][2], LOG2E, ebv[j].x);
            float u3 = fmaf(d[j][3], LOG2E, ebv[j].z);
            float g0 = fmaxf(u0, 0.f) + lg2f(1.f + ex2f(-fabsf(u0)));
            float g1 = fmaxf(u1, 0.f) + lg2f(1.f + ex2f(-fabsf(u1)));
            float g2 = fmaxf(u2, 0.f) + lg2f(1.f + ex2f(-fabsf(u2)));
            float g3 = fmaxf(u3, 0.f) + lg2f(1.f + ex2f(-fabsf(u3)));
            sA = fmaf(g0, ebv[j].y, sA);
            sA = fmaf(g1, ebv[j].w, sA);
            sB = fmaf(g2, ebv[j].y, sB);
            sB = fmaf(g3, ebv[j].w, sB);
        }
        sA += __shfl_xor_sync(0xffffffffu, sA, 1);
        sA += __shfl_xor_sync(0xffffffffu, sA, 2);
        sB += __shfl_xor_sync(0xffffffffu, sB, 1);
        sB += __shfl_xor_sync(0xffffffffu, sB, 2);
        if ((lane & 3) == 0) {
            radbuf[rowbase + (lane >> 2)]     = sA;
            radbuf[rowbase + 8 + (lane >> 2)] = sB;
        }
        __syncthreads();

        // ---- per-pair tail (first 128 threads) ----
        if (tid < MTILE) {
            float rad = radbuf[tid] + bias2;
            int b = t * MTILE + tid;
            const float* rp = rij + ((size_t)a * NN + b) * 3;
            float rx = rp[0], ry = rp[1], rz = rp[2];
            float d2  = fmaf(rx, rx, fmaf(ry, ry, rz * rz));
            float inv = rsqrtf(fmaxf(d2, 1e-8f));      // norm_with_epsilon
            float m   = (d2 < 1e-16f) ? 0.f : rad;     // dij < 1e-8 mask
            float sc  = m * inv;
            float ux = rx * sc, uy = ry * sc, uz = rz * sc;
            const float* lp = layer_input + b * 3;     // L2-hot
            float lx = lp[0], ly = lp[1], lz = lp[2];
            o0 = fmaf(uy, lz, o0); o0 = fmaf(-uz, ly, o0);
            o1 = fmaf(uz, lx, o1); o1 = fmaf(-ux, lz, o1);
            o2 = fmaf(ux, ly, o2); o2 = fmaf(-uy, lx, o2);
        }
        __syncthreads();   // radbuf reuse safety
    }

    // ---- reduction over the 4 accumulating warps ----
    if (tid < MTILE) {
        #pragma unroll
        for (int off = 16; off > 0; off >>= 1) {
            o0 += __shfl_down_sync(0xffffffffu, o0, off);
            o1 += __shfl_down_sync(0xffffffffu, o1, off);
            o2 += __shfl_down_sync(0xffffffffu, o2, off);
        }
        if (lane == 0) { redbuf[0][wid] = o0; redbuf[1][wid] = o1; redbuf[2][wid] = o2; }
    }
    __syncthreads();
    if (tid == 0) {
        float s0 = 0.f, s1 = 0.f, s2 = 0.f;
        #pragma unroll
        for (int w = 0; w < 4; w++) {
            s0 += redbuf[0][w]; s1 += redbuf[1][w]; s2 += redbuf[2][w];
        }
        out[a * 3 + 0] = s0;
        out[a * 3 + 1] = s1;
        out[a * 3 + 2] = s2;
    }
}

extern "C" void kernel_launch(void* const* d_in, const int* in_sizes, int n_in,
                              void* d_out, int out_size) {
    const float* layer_input = (const float*)d_in[0];
    const float* rbf         = (const float*)d_in[1];
    const float* rij         = (const float*)d_in[2];
    const float* W1          = (const float*)d_in[3];
    const float* b1          = (const float*)d_in[4];
    const float* W2          = (const float*)d_in[5];
    const float* b2          = (const float*)d_in[6];
    float* out = (float*)d_out;

    f1o1_mma_kernel<<<NN, TPB>>>(layer_input, rbf, rij, W1, b1, W2, b2, out);
}

// round 13
// speedup vs baseline: 1.2680x; 1.2680x over previous
#include <cuda_runtime.h>
#include <cuda_bf16.h>
#include <cstdint>

#define NN      2048
#define RBF     32
#define TPB     128
#define MTILE   128
#define NTILES  (NN / MTILE)   // 16
#define APITCH  80             // bytes per 32-bf16 row; 20-bank step -> conflict-free ldmatrix

#define LOG2E 1.4426950408889634f
#define LN2   0.6931471805599453f

// ---------------- helpers ----------------
__device__ __forceinline__ uint32_t smem_u32(const void* p) {
    return (uint32_t)__cvta_generic_to_shared(p);
}
__device__ __forceinline__ void ldmatrix_x4(uint32_t addr, uint32_t& r0, uint32_t& r1,
                                            uint32_t& r2, uint32_t& r3) {
    asm volatile("ldmatrix.sync.aligned.m8n8.x4.shared.b16 {%0,%1,%2,%3}, [%4];"
                 : "=r"(r0), "=r"(r1), "=r"(r2), "=r"(r3) : "r"(addr));
}
__device__ __forceinline__ void mma_bf16(float& d0, float& d1, float& d2, float& d3,
                                         uint32_t a0, uint32_t a1, uint32_t a2, uint32_t a3,
                                         uint32_t b0, uint32_t b1) {
    asm volatile("mma.sync.aligned.m16n8k16.row.col.f32.bf16.bf16.f32 "
                 "{%0,%1,%2,%3}, {%4,%5,%6,%7}, {%8,%9}, {%0,%1,%2,%3};"
                 : "+f"(d0), "+f"(d1), "+f"(d2), "+f"(d3)
                 : "r"(a0), "r"(a1), "r"(a2), "r"(a3), "r"(b0), "r"(b1));
}
__device__ __forceinline__ float ex2f(float x) {
    float y; asm("ex2.approx.f32 %0, %1;" : "=f"(y) : "f"(x)); return y;
}
__device__ __forceinline__ float lg2f(float x) {
    float y; asm("lg2.approx.f32 %0, %1;" : "=f"(y) : "f"(x)); return y;
}
__device__ __forceinline__ uint32_t bits2(__nv_bfloat162 v) {
    return *(uint32_t*)&v;
}

// ---------------- kernel ----------------
// One block per 'a'; 4 warps, each fully owning 32 rows of every 128-row tile:
//   LDG own 4KB slab -> regs -> bf16 hi/lo split -> STS own A-slab ->
//   __syncwarp -> ldmatrix -> mma.sync (3 split products) -> log2-softplus
//   epilogue -> cross accumulate. NO __syncthreads in the tile loop; register
//   double-buffering overlaps next tile's LDG with this tile's math.
__global__ __launch_bounds__(TPB, 4) void f1o1_mma_kernel(
    const float* __restrict__ layer_input,  // [NN,1,3]
    const float* __restrict__ rbf,          // [NN,NN,RBF]
    const float* __restrict__ rij,          // [NN,NN,3]
    const float* __restrict__ W1,           // [RBF,RBF] (k,h)
    const float* __restrict__ b1,           // [RBF]
    const float* __restrict__ W2,           // [RBF,1]
    const float* __restrict__ b2,           // [1]
    float* __restrict__ out)                // [NN,1,3]
{
    __shared__ __align__(16) char  AhT[MTILE * APITCH]; // 10 KB bf16 hi
    __shared__ __align__(16) char  AlT[MTILE * APITCH]; // 10 KB bf16 lo
    __shared__ __align__(16) char  BhT[RBF * APITCH];   // 2.5 KB W1^T hi
    __shared__ __align__(16) char  BlT[RBF * APITCH];   // 2.5 KB W1^T lo
    __shared__ __align__(16) float2 eb[RBF];            // {b1*log2e, w2*ln2}
    __shared__ float radbuf[4][32];
    __shared__ float redbuf[3][4];

    const int tid  = threadIdx.x;
    const int lane = tid & 31;
    const int wid  = tid >> 5;
    const int a    = blockIdx.x;
    const uint32_t AH = smem_u32(AhT), AL = smem_u32(AlT);
    const uint32_t BH = smem_u32(BhT), BL = smem_u32(BlT);

    // ---- build B = W1^T split hi/lo + folded epilogue constants ----
    for (int e = tid; e < RBF * RBF; e += TPB) {
        int k = e >> 5, h = e & 31;
        float w = W1[e];
        __nv_bfloat16 hb = __float2bfloat16(w);
        __nv_bfloat16 lb = __float2bfloat16(w - __bfloat162float(hb));
        *(unsigned short*)(BhT + h * APITCH + k * 2) = *(unsigned short*)&hb;
        *(unsigned short*)(BlT + h * APITCH + k * 2) = *(unsigned short*)&lb;
    }
    if (tid < RBF) eb[tid] = make_float2(b1[tid] * LOG2E, W2[tid] * LN2);
    const float bias2 = b2[0];
    __syncthreads();

    // ---- per-thread folded constants {b1e, w2l} for h = 8j+2c, +1 ----
    float4 ebv[4];
    {
        int c = lane & 3;
        #pragma unroll
        for (int j = 0; j < 4; j++)
            ebv[j] = *(const float4*)&eb[8 * j + 2 * c];
    }

    // ---- preload B-hi fragments (resident, validated q-trick layout) ----
    uint32_t bh[4][2][2];
    {
        int q = lane >> 3, l8 = lane & 7;
        #pragma unroll
        for (int s = 0; s < 2; s++) {
            uint32_t off0 = (uint32_t)((8 * (q >> 1) + l8) * APITCH
                                       + (16 * s + 8 * (q & 1)) * 2);
            ldmatrix_x4(BH + off0, bh[0][s][0], bh[0][s][1], bh[1][s][0], bh[1][s][1]);
            uint32_t off1 = (uint32_t)((8 * (2 + (q >> 1)) + l8) * APITCH
                                       + (16 * s + 8 * (q & 1)) * 2);
            ldmatrix_x4(BH + off1, bh[2][s][0], bh[2][s][1], bh[3][s][0], bh[3][s][1]);
        }
    }

    // ---- initial LDG: this warp's 4 KB slab of tile 0 ----
    float4 v[8];
    {
        const float4* gw = (const float4*)(rbf + ((size_t)a * NN + wid * 32) * RBF);
        #pragma unroll
        for (int j = 0; j < 8; j++) v[j] = gw[lane + 32 * j];
    }

    float o0 = 0.f, o1 = 0.f, o2 = 0.f;

    #pragma unroll 1
    for (int t = 0; t < NTILES; t++) {
        // ---- convert regs -> bf16 hi/lo into this warp's A-slab rows ----
        #pragma unroll
        for (int j = 0; j < 8; j++) {
            int f  = lane + 32 * j;           // float4 index in warp slab
            int rl = f >> 3, kq = f & 7;      // row-local 0..31, k-quad 0..7
            int row = wid * 32 + rl;
            float4 w = v[j];
            __nv_bfloat162 h0 = __floats2bfloat162_rn(w.x, w.y);
            __nv_bfloat162 h1 = __floats2bfloat162_rn(w.z, w.w);
            float2 r0 = __bfloat1622float2(h0);
            float2 r1 = __bfloat1622float2(h1);
            __nv_bfloat162 l0 = __floats2bfloat162_rn(w.x - r0.x, w.y - r0.y);
            __nv_bfloat162 l1 = __floats2bfloat162_rn(w.z - r1.x, w.w - r1.y);
            *(uint2*)(AhT + row * APITCH + kq * 8) = make_uint2(bits2(h0), bits2(h1));
            *(uint2*)(AlT + row * APITCH + kq * 8) = make_uint2(bits2(l0), bits2(l1));
        }

        // ---- prefetch next tile's slab into v (overlaps MMA/epilogue) ----
        if (t + 1 < NTILES) {
            const float4* gw = (const float4*)(
                rbf + ((size_t)a * NN + (t + 1) * MTILE + wid * 32) * RBF);
            #pragma unroll
            for (int j = 0; j < 8; j++) v[j] = gw[lane + 32 * j];
        }

        __syncwarp();   // also orders prev tail's radbuf reads before epilogue writes

        // ---- MMA over this warp's 32 rows (2 m-subtiles of 16) ----
        #pragma unroll
        for (int ms = 0; ms < 2; ms++) {
            float d[4][4];
            #pragma unroll
            for (int j = 0; j < 4; j++)
                #pragma unroll
                for (int r = 0; r < 4; r++) d[j][r] = 0.f;

            const int rowbase = wid * 32 + ms * 16;
            #pragma unroll
            for (int s = 0; s < 2; s++) {
                uint32_t aoff = (uint32_t)((rowbase + (lane & 15)) * APITCH
                                           + (16 * s + 8 * (lane >> 4)) * 2);
                uint32_t ah0, ah1, ah2, ah3, al0, al1, al2, al3;
                ldmatrix_x4(AH + aoff, ah0, ah1, ah2, ah3);
                ldmatrix_x4(AL + aoff, al0, al1, al2, al3);

                uint32_t bl[4][2];
                {
                    int q = lane >> 3, l8 = lane & 7;
                    uint32_t off0 = (uint32_t)((8 * (q >> 1) + l8) * APITCH
                                               + (16 * s + 8 * (q & 1)) * 2);
                    ldmatrix_x4(BL + off0, bl[0][0], bl[0][1], bl[1][0], bl[1][1]);
                    uint32_t off1 = (uint32_t)((8 * (2 + (q >> 1)) + l8) * APITCH
                                               + (16 * s + 8 * (q & 1)) * 2);
                    ldmatrix_x4(BL + off1, bl[2][0], bl[2][1], bl[3][0], bl[3][1]);
                }

                #pragma unroll
                for (int j = 0; j < 4; j++) {
                    mma_bf16(d[j][0], d[j][1], d[j][2], d[j][3],
                             ah0, ah1, ah2, ah3, bh[j][s][0], bh[j][s][1]);
                    mma_bf16(d[j][0], d[j][1], d[j][2], d[j][3],
                             al0, al1, al2, al3, bh[j][s][0], bh[j][s][1]);
                    mma_bf16(d[j][0], d[j][1], d[j][2], d[j][3],
                             ah0, ah1, ah2, ah3, bl[j][0], bl[j][1]);
                }
            }

            // ---- epilogue: log2-domain softplus + W2 dot ----
            float sA = 0.f, sB = 0.f;    // rows g, g+8 of this 16-row subtile
            #pragma unroll
            for (int j = 0; j < 4; j++) {
                float u0 = fmaf(d[j][0], LOG2E, ebv[j].x);
                float u1 = fmaf(d[j][1], LOG2E, ebv[j].z);
                float u2 = fmaf(d[j][2], LOG2E, ebv[j].x);
                float u3 = fmaf(d[j][3], LOG2E, ebv[j].z);
                float g0 = fmaxf(u0, 0.f) + lg2f(1.f + ex2f(-fabsf(u0)));
                float g1 = fmaxf(u1, 0.f) + lg2f(1.f + ex2f(-fabsf(u1)));
                float g2 = fmaxf(u2, 0.f) + lg2f(1.f + ex2f(-fabsf(u2)));
                float g3 = fmaxf(u3, 0.f) + lg2f(1.f + ex2f(-fabsf(u3)));
                sA = fmaf(g0, ebv[j].y, sA);
                sA = fmaf(g1, ebv[j].w, sA);
                sB = fmaf(g2, ebv[j].y, sB);
                sB = fmaf(g3, ebv[j].w, sB);
            }
            sA += __shfl_xor_sync(0xffffffffu, sA, 1);
            sA += __shfl_xor_sync(0xffffffffu, sA, 2);
            sB += __shfl_xor_sync(0xffffffffu, sB, 1);
            sB += __shfl_xor_sync(0xffffffffu, sB, 2);
            if ((lane & 3) == 0) {
                radbuf[wid][ms * 16 + (lane >> 2)]     = sA;
                radbuf[wid][ms * 16 + 8 + (lane >> 2)] = sB;
            }
        }
        __syncwarp();

        // ---- per-pair tail: this warp's 32 pairs ----
        {
            float rad = radbuf[wid][lane] + bias2;
            int b = t * MTILE + wid * 32 + lane;
            const float* rp = rij + ((size_t)a * NN + b) * 3;
            float rx = rp[0], ry = rp[1], rz = rp[2];
            float d2  = fmaf(rx, rx, fmaf(ry, ry, rz * rz));
            float inv = rsqrtf(fmaxf(d2, 1e-8f));      // norm_with_epsilon
            float m   = (d2 < 1e-16f) ? 0.f : rad;     // dij < 1e-8 mask
            float sc  = m * inv;
            float ux = rx * sc, uy = ry * sc, uz = rz * sc;
            const float* lp = layer_input + b * 3;     // L2-hot
            float lx = lp[0], ly = lp[1], lz = lp[2];
            o0 = fmaf(uy, lz, o0); o0 = fmaf(-uz, ly, o0);
            o1 = fmaf(uz, lx, o1); o1 = fmaf(-ux, lz, o1);
            o2 = fmaf(ux, ly, o2); o2 = fmaf(-uy, lx, o2);
        }
        // next iteration's convert writes a different smem region (A tiles),
        // and its __syncwarp orders radbuf reuse — no block sync needed.
    }

    // ---- final reduction: warp shuffles + cross-warp smem ----
    #pragma unroll
    for (int off = 16; off > 0; off >>= 1) {
        o0 += __shfl_down_sync(0xffffffffu, o0, off);
        o1 += __shfl_down_sync(0xffffffffu, o1, off);
        o2 += __shfl_down_sync(0xffffffffu, o2, off);
    }
    if (lane == 0) { redbuf[0][wid] = o0; redbuf[1][wid] = o1; redbuf[2][wid] = o2; }
    __syncthreads();
    if (tid == 0) {
        float s0 = 0.f, s1 = 0.f, s2 = 0.f;
        #pragma unroll
        for (int w = 0; w < 4; w++) {
            s0 += redbuf[0][w]; s1 += redbuf[1][w]; s2 += redbuf[2][w];
        }
        out[a * 3 + 0] = s0;
        out[a * 3 + 1] = s1;
        out[a * 3 + 2] = s2;
    }
}

extern "C" void kernel_launch(void* const* d_in, const int* in_sizes, int n_in,
                              void* d_out, int out_size) {
    const float* layer_input = (const float*)d_in[0];
    const float* rbf         = (const float*)d_in[1];
    const float* rij         = (const float*)d_in[2];
    const float* W1          = (const float*)d_in[3];
    const float* b1          = (const float*)d_in[4];
    const float* W2          = (const float*)d_in[5];
    const float* b2          = (const float*)d_in[6];
    float* out = (float*)d_out;

    f1o1_mma_kernel<<<NN, TPB>>>(layer_input, rbf, rij, W1, b1, W2, b2, out);
}